// round 6
// baseline (speedup 1.0000x reference)
#include <cuda_runtime.h>
#include <cuda_bf16.h>
#include <stdint.h>

#define D 128
#define E_CAP 16384
#define N_CAP 65536
#define NNZ_CAP (1 << 20)
#define EPS 1e-8f
#define CHUNK 4096
#define NBLK_E (E_CAP / CHUNK)            // 4
#define NBLK_N (N_CAP / CHUNK)            // 16
#define NBLK_SCAN (NBLK_E + NBLK_N)       // 20

// ---------------- scratch (static device globals; no allocation) ------------
__device__ float    g_z[(size_t)N_CAP * D];          // z = agg(x) + x (fp32)
__device__ unsigned g_x_h[(size_t)N_CAP * 64];       // bf16x2 mirror of x
__device__ unsigned g_heattr_h[(size_t)E_CAP * 64];  // bf16x2 hyperedge attr
__device__ int g_eidx[NNZ_CAP];
__device__ int g_nidx[NNZ_CAP];
__device__ int g_eoff[E_CAP + 1];
__device__ int g_noff[N_CAP + 1];
__device__ int g_cnts[E_CAP + N_CAP];                // counts, then reused as cursors
__device__ int g_bsum[NBLK_SCAN];
__device__ int g_is64;

#define ECNT (g_cnts)
#define NCNT (g_cnts + E_CAP)

// ---------------- zero counters + index dtype detect -------------------------
__global__ void zero_cnts_kernel(const int* __restrict__ h) {
    int i = blockIdx.x * blockDim.x + threadIdx.x;
    ((int4*)g_cnts)[i] = make_int4(0, 0, 0, 0);
    if (i == 0)
        g_is64 = (h[1] == 0 && h[3] == 0 && h[5] == 0 && h[7] == 0) ? 1 : 0;
}

// ---------------- bf16 mirror of x -------------------------------------------
__global__ __launch_bounds__(256) void mirror_kernel(const float* __restrict__ x, int n4) {
    int i = blockIdx.x * blockDim.x + threadIdx.x;  // one float4 each
    if (i >= n4) return;
    float4 v = ((const float4*)x)[i];
    uint2 h;
    asm("cvt.rn.bf16x2.f32 %0, %1, %2;" : "=r"(h.x) : "f"(v.y), "f"(v.x));
    asm("cvt.rn.bf16x2.f32 %0, %1, %2;" : "=r"(h.y) : "f"(v.w), "f"(v.z));
    ((uint2*)g_x_h)[i] = h;
}

// ---------------- CSR build: histogram (4 entries / thread) ------------------
__global__ __launch_bounds__(256) void hist_kernel(const void* __restrict__ base, int nnz) {
    int i0 = (blockIdx.x * blockDim.x + threadIdx.x) * 4;
    if (i0 >= nnz) return;
    int m = nnz - i0; if (m > 4) m = 4;
    int src[4], e[4];
    if (g_is64) {
        const long long* p = (const long long*)base;
        #pragma unroll
        for (int k = 0; k < 4; k++) {
            int i = i0 + ((k < m) ? k : 0);
            src[k] = (int)__ldg(p + i);
            e[k]   = (int)__ldg(p + nnz + i);
        }
    } else {
        const int* p = (const int*)base;
        #pragma unroll
        for (int k = 0; k < 4; k++) {
            int i = i0 + ((k < m) ? k : 0);
            src[k] = __ldg(p + i);
            e[k]   = __ldg(p + nnz + i);
        }
    }
    #pragma unroll
    for (int k = 0; k < 4; k++) {
        if (k < m) {
            atomicAdd(&ECNT[e[k]], 1);
            atomicAdd(&NCNT[src[k]], 1);
        }
    }
}

// ---------------- CSR build: 2-level exclusive scan --------------------------
__global__ __launch_bounds__(1024) void scan_local_kernel() {
    int b = blockIdx.x;
    const int* cnt; int* off; int lo;
    if (b < NBLK_E) { cnt = ECNT; off = g_eoff; lo = b * CHUNK; }
    else            { cnt = NCNT; off = g_noff; lo = (b - NBLK_E) * CHUNK; }

    __shared__ int wsum[32];
    int tid = threadIdx.x, lane = tid & 31, wid = tid >> 5;
    int idx = lo + tid * 4;

    int4 v = *(const int4*)(cnt + idx);
    int tsum = v.x + v.y + v.z + v.w;
    int incl = tsum;
    #pragma unroll
    for (int s = 1; s < 32; s <<= 1) {
        int t = __shfl_up_sync(0xffffffffu, incl, s);
        if (lane >= s) incl += t;
    }
    if (lane == 31) wsum[wid] = incl;
    __syncthreads();
    if (wid == 0) {
        int w = wsum[lane];
        int wi = w;
        #pragma unroll
        for (int s = 1; s < 32; s <<= 1) {
            int t = __shfl_up_sync(0xffffffffu, wi, s);
            if (lane >= s) wi += t;
        }
        wsum[lane] = wi - w;
    }
    __syncthreads();
    int ex = wsum[wid] + incl - tsum;
    off[idx]     = ex;
    off[idx + 1] = ex + v.x;
    off[idx + 2] = ex + v.x + v.y;
    off[idx + 3] = ex + v.x + v.y + v.z;
    if (tid == 1023) g_bsum[b] = ex + tsum;
}

// fixup adds cross-block base AND initializes cursors (= start offsets)
__global__ __launch_bounds__(1024) void scan_fixup_kernel() {
    int b = blockIdx.x;
    __shared__ int s_base;
    int tid = threadIdx.x;
    if (tid == 0) {
        int start = (b < NBLK_E) ? 0 : NBLK_E;
        int base = 0;
        for (int i = start; i < b; i++) base += g_bsum[i];
        s_base = base;
    }
    __syncthreads();
    int base = s_base;
    int* off; int* cur; int lo;
    if (b < NBLK_E) { off = g_eoff; cur = ECNT; lo = b * CHUNK; }
    else            { off = g_noff; cur = NCNT; lo = (b - NBLK_E) * CHUNK; }
    int idx = lo + tid * 4;
    int4 o = *(int4*)(off + idx);
    o.x += base; o.y += base; o.z += base; o.w += base;
    *(int4*)(off + idx) = o;
    *(int4*)(cur + idx) = o;   // cursors start at segment start
    if (tid == 0) {
        if (b == NBLK_E - 1)    g_eoff[E_CAP] = base + g_bsum[b];
        if (b == NBLK_SCAN - 1) g_noff[N_CAP] = base + g_bsum[b];
    }
}

// ---------------- CSR build: bucket fill (cursor atomics, 4/thread) ----------
__global__ __launch_bounds__(256) void fill_kernel(const void* __restrict__ base, int nnz) {
    int i0 = (blockIdx.x * blockDim.x + threadIdx.x) * 4;
    if (i0 >= nnz) return;
    int m = nnz - i0; if (m > 4) m = 4;
    int src[4], e[4];
    if (g_is64) {
        const long long* p = (const long long*)base;
        #pragma unroll
        for (int k = 0; k < 4; k++) {
            int i = i0 + ((k < m) ? k : 0);
            src[k] = (int)__ldg(p + i);
            e[k]   = (int)__ldg(p + nnz + i);
        }
    } else {
        const int* p = (const int*)base;
        #pragma unroll
        for (int k = 0; k < 4; k++) {
            int i = i0 + ((k < m) ? k : 0);
            src[k] = __ldg(p + i);
            e[k]   = __ldg(p + nnz + i);
        }
    }
    #pragma unroll
    for (int k = 0; k < 4; k++) {
        if (k < m) {
            int pe = atomicAdd(&ECNT[e[k]], 1);
            g_eidx[pe] = src[k];
            int pn = atomicAdd(&NCNT[src[k]], 1);
            g_nidx[pn] = e[k];
        }
    }
}

// ---------------- phase A: per-edge pull reduction on x mirror ---------------
__global__ __launch_bounds__(128) void edge_agg_kernel() {
    int half = threadIdx.x >> 6;
    int t = threadIdx.x & 63;
    int e = blockIdx.x * 2 + half;
    int beg = g_eoff[e], end = g_eoff[e + 1];
    if (beg == end) return;

    float s0a = 0.f, s1a = 0.f, s0b = 0.f, s1b = 0.f;
    int j = beg;
    for (; j + 2 <= end; j += 2) {
        int n0 = g_eidx[j], n1 = g_eidx[j + 1];
        unsigned u0 = g_x_h[(size_t)n0 * 64 + t];
        unsigned u1 = g_x_h[(size_t)n1 * 64 + t];
        s0a += __uint_as_float(u0 << 16);
        s1a += __uint_as_float(u0 & 0xffff0000u);
        s0b += __uint_as_float(u1 << 16);
        s1b += __uint_as_float(u1 & 0xffff0000u);
    }
    if (j < end) {
        unsigned u = g_x_h[(size_t)g_eidx[j] * 64 + t];
        s0a += __uint_as_float(u << 16);
        s1a += __uint_as_float(u & 0xffff0000u);
    }
    float inv = 1.0f / ((float)(end - beg) + EPS);
    float f0 = (s0a + s0b) * inv;
    float f1 = (s1a + s1b) * inv;
    unsigned r;
    asm("cvt.rn.bf16x2.f32 %0, %1, %2;" : "=r"(r) : "f"(f1), "f"(f0));
    g_heattr_h[(size_t)e * 64 + t] = r;
}

// ---------------- phase B: per-node pull -> z = agg + x ----------------------
__global__ __launch_bounds__(256) void node_agg_kernel(const float* __restrict__ x,
                                                       int row_base, int row_end) {
    int w = row_base + ((blockIdx.x * blockDim.x + threadIdx.x) >> 5);
    if (w >= row_end) return;
    int lane = threadIdx.x & 31;
    int beg = g_noff[w], end = g_noff[w + 1];

    float4 a = make_float4(0.f, 0.f, 0.f, 0.f);
    float4 a2 = make_float4(0.f, 0.f, 0.f, 0.f);
    int j = beg;
    for (; j + 2 <= end; j += 2) {
        int e0 = g_nidx[j], e1 = g_nidx[j + 1];
        uint2 u0 = *(const uint2*)(g_heattr_h + (size_t)e0 * 64 + lane * 2);
        uint2 u1 = *(const uint2*)(g_heattr_h + (size_t)e1 * 64 + lane * 2);
        a.x  += __uint_as_float(u0.x << 16);
        a.y  += __uint_as_float(u0.x & 0xffff0000u);
        a.z  += __uint_as_float(u0.y << 16);
        a.w  += __uint_as_float(u0.y & 0xffff0000u);
        a2.x += __uint_as_float(u1.x << 16);
        a2.y += __uint_as_float(u1.x & 0xffff0000u);
        a2.z += __uint_as_float(u1.y << 16);
        a2.w += __uint_as_float(u1.y & 0xffff0000u);
    }
    if (j < end) {
        uint2 u = *(const uint2*)(g_heattr_h + (size_t)g_nidx[j] * 64 + lane * 2);
        a.x += __uint_as_float(u.x << 16);
        a.y += __uint_as_float(u.x & 0xffff0000u);
        a.z += __uint_as_float(u.y << 16);
        a.w += __uint_as_float(u.y & 0xffff0000u);
    }

    float s = 1.0f / ((float)(end - beg) + EPS);
    float4 xr = ((const float4*)x)[(size_t)w * 32 + lane];
    float4 z;
    z.x = (a.x + a2.x) * s + xr.x;
    z.y = (a.y + a2.y) * s + xr.y;
    z.z = (a.z + a2.z) * s + xr.z;
    z.w = (a.w + a2.w) * s + xr.w;
    ((float4*)g_z)[(size_t)w * 32 + lane] = z;
}

// ---------------- GEMM: out = z @ W^T + bias (packed f32x2 FMA) --------------
#define WT_STRIDE 132
#define GEMM_SMEM ((128 * WT_STRIDE + 64 * WT_STRIDE) * 4)

__device__ __forceinline__ unsigned long long fma2(unsigned long long a,
                                                   unsigned long long b,
                                                   unsigned long long c) {
    unsigned long long d;
    asm("fma.rn.f32x2 %0, %1, %2, %3;" : "=l"(d) : "l"(a), "l"(b), "l"(c));
    return d;
}

__global__ __launch_bounds__(256) void gemm_kernel(const float* __restrict__ W,
                                                   const float* __restrict__ bias,
                                                   float* __restrict__ out,
                                                   int row_base, int N) {
    extern __shared__ float sm[];
    float* WT = sm;                       // [128][132], WT[k][j] = W[j][k]
    float* Xs = sm + 128 * WT_STRIDE;     // [64][132]

    int t = threadIdx.x;
    int row0 = row_base + blockIdx.x * 64;

    #pragma unroll
    for (int i = 0; i < 64; i++) {
        int idx = t + i * 256;
        int j = idx >> 7, k = idx & 127;
        WT[k * WT_STRIDE + j] = W[idx];
    }
    #pragma unroll
    for (int i = 0; i < 32; i++) {
        int idx = t + i * 256;
        int r = idx >> 7, k = idx & 127;
        int row = row0 + r;
        if (row >= N) row = N - 1;
        Xs[r * WT_STRIDE + k] = g_z[(size_t)row * D + k];
    }
    __syncthreads();

    int tx = t & 15, ty = t >> 4;
    int c0 = tx * 8, r0 = ty * 4;

    float4 b0 = *(const float4*)(bias + c0);
    float4 b1 = *(const float4*)(bias + c0 + 4);

    unsigned long long acc[4][4];
    #pragma unroll
    for (int i = 0; i < 4; i++)
        #pragma unroll
        for (int j = 0; j < 4; j++) acc[i][j] = 0ull;

    #pragma unroll 4
    for (int k = 0; k < 128; k++) {
        ulonglong2 wa = *(const ulonglong2*)(WT + k * WT_STRIDE + c0);
        ulonglong2 wb = *(const ulonglong2*)(WT + k * WT_STRIDE + c0 + 4);
        #pragma unroll
        for (int i = 0; i < 4; i++) {
            unsigned au = __float_as_uint(Xs[(r0 + i) * WT_STRIDE + k]);
            unsigned long long aa;
            asm("mov.b64 %0, {%1, %1};" : "=l"(aa) : "r"(au));
            acc[i][0] = fma2(aa, wa.x, acc[i][0]);
            acc[i][1] = fma2(aa, wa.y, acc[i][1]);
            acc[i][2] = fma2(aa, wb.x, acc[i][2]);
            acc[i][3] = fma2(aa, wb.y, acc[i][3]);
        }
    }

    #pragma unroll
    for (int i = 0; i < 4; i++) {
        int row = row0 + r0 + i;
        if (row < N) {
            float2 p0 = *(float2*)&acc[i][0];
            float2 p1 = *(float2*)&acc[i][1];
            float2 p2 = *(float2*)&acc[i][2];
            float2 p3 = *(float2*)&acc[i][3];
            float4 o0 = make_float4(p0.x + b0.x, p0.y + b0.y, p1.x + b0.z, p1.y + b0.w);
            float4 o1 = make_float4(p2.x + b1.x, p2.y + b1.y, p3.x + b1.z, p3.y + b1.w);
            *(float4*)(out + (size_t)row * D + c0)     = o0;
            *(float4*)(out + (size_t)row * D + c0 + 4) = o1;
        }
    }
}

// ---------------- launch -----------------------------------------------------
extern "C" void kernel_launch(void* const* d_in, const int* in_sizes, int n_in,
                              void* d_out, int out_size) {
    const float* x    = (const float*)d_in[0];
    const void*  hidx = d_in[1];
    const float* W    = (const float*)d_in[2];
    const float* bias = (const float*)d_in[3];
    float* out = (float*)d_out;

    int N   = in_sizes[0] / D;
    int nnz = in_sizes[1] / 2;

    static cudaStream_t s2 = 0;
    static cudaEvent_t evA = 0, evM = 0, ev0 = 0, ev2 = 0;
    if (!s2) {
        cudaStreamCreateWithFlags(&s2, cudaStreamNonBlocking);
        cudaEventCreateWithFlags(&evA, cudaEventDisableTiming);
        cudaEventCreateWithFlags(&evM, cudaEventDisableTiming);
        cudaEventCreateWithFlags(&ev0, cudaEventDisableTiming);
        cudaEventCreateWithFlags(&ev2, cudaEventDisableTiming);
        cudaFuncSetAttribute(gemm_kernel,
                             cudaFuncAttributeMaxDynamicSharedMemorySize, GEMM_SMEM);
    }

    // fork: mirror of x on s2, CSR build on capture stream
    cudaEventRecord(evA, 0);
    cudaStreamWaitEvent(s2, evA, 0);
    int n4 = N * (D / 4);
    mirror_kernel<<<(n4 + 255) / 256, 256, 0, s2>>>(x, n4);
    cudaEventRecord(evM, s2);

    zero_cnts_kernel<<<(E_CAP + N_CAP) / 4 / 256, 256>>>((const int*)hidx);
    int q = (nnz + 3) / 4;
    hist_kernel<<<(q + 255) / 256, 256>>>(hidx, nnz);
    scan_local_kernel<<<NBLK_SCAN, 1024>>>();
    scan_fixup_kernel<<<NBLK_SCAN, 1024>>>();
    fill_kernel<<<(q + 255) / 256, 256>>>(hidx, nnz);

    // join mirror before edge_agg
    cudaStreamWaitEvent(0, evM, 0);
    edge_agg_kernel<<<E_CAP / 2, 128>>>();

    // pipelined tail: node_agg(p0) -> { gemm(p0) || node_agg(p1) -> gemm(p1) }
    int half_rows = ((N / 2) + 63) & ~63;     // multiple of 64
    if (half_rows > N) half_rows = N;
    int rows1 = N - half_rows;

    node_agg_kernel<<<(half_rows + 7) / 8, 256>>>(x, 0, half_rows);
    cudaEventRecord(ev0, 0);

    gemm_kernel<<<half_rows / 64, 256, GEMM_SMEM>>>(W, bias, out, 0, N);

    cudaStreamWaitEvent(s2, ev0, 0);
    if (rows1 > 0) {
        node_agg_kernel<<<(rows1 + 7) / 8, 256, 0, s2>>>(x, half_rows, N);
        gemm_kernel<<<(rows1 + 63) / 64, 256, GEMM_SMEM, s2>>>(W, bias, out, half_rows, N);
    }
    cudaEventRecord(ev2, s2);
    cudaStreamWaitEvent(0, ev2, 0);
}

// round 7
// speedup vs baseline: 1.0882x; 1.0882x over previous
#include <cuda_runtime.h>
#include <cuda_bf16.h>
#include <stdint.h>

#define D 128
#define E_CAP 16384
#define N_CAP 65536
#define NNZ_CAP (1 << 20)
#define EPS 1e-8f
#define CHUNK 4096
#define NBLK_E (E_CAP / CHUNK)            // 4
#define NBLK_N (N_CAP / CHUNK)            // 16
#define NBLK_SCAN (NBLK_E + NBLK_N)       // 20

// ---------------- scratch (static device globals; no allocation) ------------
__device__ float    g_xnode[(size_t)N_CAP * D];      // fp32 x@W^T (exact residual)
__device__ unsigned g_xnode_h[(size_t)N_CAP * 64];   // bf16x2 gather mirror
__device__ unsigned g_heattr_h[(size_t)E_CAP * 64];  // bf16x2 hyperedge attr
__device__ int g_eidx[NNZ_CAP];
__device__ int g_nidx[NNZ_CAP];
__device__ int g_eoff[E_CAP + 1];
__device__ int g_noff[N_CAP + 1];
__device__ int g_cnts[E_CAP + N_CAP];                // counts, then reused as cursors
__device__ int g_bsum[NBLK_SCAN];
__device__ int g_is64;

#define ECNT (g_cnts)
#define NCNT (g_cnts + E_CAP)

// ---------------- zero counters + index dtype detect -------------------------
__global__ void zero_cnts_kernel(const int* __restrict__ h) {
    int i = blockIdx.x * blockDim.x + threadIdx.x;
    ((int4*)g_cnts)[i] = make_int4(0, 0, 0, 0);
    if (i == 0)
        g_is64 = (h[1] == 0 && h[3] == 0 && h[5] == 0 && h[7] == 0) ? 1 : 0;
}

// ---------------- CSR build: histogram (4 entries / thread) ------------------
__global__ __launch_bounds__(256) void hist_kernel(const void* __restrict__ base, int nnz) {
    int i0 = (blockIdx.x * blockDim.x + threadIdx.x) * 4;
    if (i0 >= nnz) return;
    int m = nnz - i0; if (m > 4) m = 4;
    int src[4], e[4];
    if (g_is64) {
        const long long* p = (const long long*)base;
        #pragma unroll
        for (int k = 0; k < 4; k++) {
            int i = i0 + ((k < m) ? k : 0);
            src[k] = (int)__ldg(p + i);
            e[k]   = (int)__ldg(p + nnz + i);
        }
    } else {
        const int* p = (const int*)base;
        #pragma unroll
        for (int k = 0; k < 4; k++) {
            int i = i0 + ((k < m) ? k : 0);
            src[k] = __ldg(p + i);
            e[k]   = __ldg(p + nnz + i);
        }
    }
    #pragma unroll
    for (int k = 0; k < 4; k++) {
        if (k < m) {
            atomicAdd(&ECNT[e[k]], 1);
            atomicAdd(&NCNT[src[k]], 1);
        }
    }
}

// ---------------- CSR build: 2-level exclusive scan --------------------------
__global__ __launch_bounds__(1024) void scan_local_kernel() {
    int b = blockIdx.x;
    const int* cnt; int* off; int lo;
    if (b < NBLK_E) { cnt = ECNT; off = g_eoff; lo = b * CHUNK; }
    else            { cnt = NCNT; off = g_noff; lo = (b - NBLK_E) * CHUNK; }

    __shared__ int wsum[32];
    int tid = threadIdx.x, lane = tid & 31, wid = tid >> 5;
    int idx = lo + tid * 4;

    int4 v = *(const int4*)(cnt + idx);
    int tsum = v.x + v.y + v.z + v.w;
    int incl = tsum;
    #pragma unroll
    for (int s = 1; s < 32; s <<= 1) {
        int t = __shfl_up_sync(0xffffffffu, incl, s);
        if (lane >= s) incl += t;
    }
    if (lane == 31) wsum[wid] = incl;
    __syncthreads();
    if (wid == 0) {
        int w = wsum[lane];
        int wi = w;
        #pragma unroll
        for (int s = 1; s < 32; s <<= 1) {
            int t = __shfl_up_sync(0xffffffffu, wi, s);
            if (lane >= s) wi += t;
        }
        wsum[lane] = wi - w;
    }
    __syncthreads();
    int ex = wsum[wid] + incl - tsum;
    off[idx]     = ex;
    off[idx + 1] = ex + v.x;
    off[idx + 2] = ex + v.x + v.y;
    off[idx + 3] = ex + v.x + v.y + v.z;
    if (tid == 1023) g_bsum[b] = ex + tsum;
}

// fixup adds cross-block base AND initializes cursors (= start offsets)
__global__ __launch_bounds__(1024) void scan_fixup_kernel() {
    int b = blockIdx.x;
    __shared__ int s_base;
    int tid = threadIdx.x;
    if (tid == 0) {
        int start = (b < NBLK_E) ? 0 : NBLK_E;
        int base = 0;
        for (int i = start; i < b; i++) base += g_bsum[i];
        s_base = base;
    }
    __syncthreads();
    int base = s_base;
    int* off; int* cur; int lo;
    if (b < NBLK_E) { off = g_eoff; cur = ECNT; lo = b * CHUNK; }
    else            { off = g_noff; cur = NCNT; lo = (b - NBLK_E) * CHUNK; }
    int idx = lo + tid * 4;
    int4 o = *(int4*)(off + idx);
    o.x += base; o.y += base; o.z += base; o.w += base;
    *(int4*)(off + idx) = o;
    *(int4*)(cur + idx) = o;   // cursors start at segment start
    if (tid == 0) {
        if (b == NBLK_E - 1)    g_eoff[E_CAP] = base + g_bsum[b];
        if (b == NBLK_SCAN - 1) g_noff[N_CAP] = base + g_bsum[b];
    }
}

// ---------------- CSR build: bucket fill (cursor atomics, 4/thread) ----------
__global__ __launch_bounds__(256) void fill_kernel(const void* __restrict__ base, int nnz) {
    int i0 = (blockIdx.x * blockDim.x + threadIdx.x) * 4;
    if (i0 >= nnz) return;
    int m = nnz - i0; if (m > 4) m = 4;
    int src[4], e[4];
    if (g_is64) {
        const long long* p = (const long long*)base;
        #pragma unroll
        for (int k = 0; k < 4; k++) {
            int i = i0 + ((k < m) ? k : 0);
            src[k] = (int)__ldg(p + i);
            e[k]   = (int)__ldg(p + nnz + i);
        }
    } else {
        const int* p = (const int*)base;
        #pragma unroll
        for (int k = 0; k < 4; k++) {
            int i = i0 + ((k < m) ? k : 0);
            src[k] = __ldg(p + i);
            e[k]   = __ldg(p + nnz + i);
        }
    }
    #pragma unroll
    for (int k = 0; k < 4; k++) {
        if (k < m) {
            int pe = atomicAdd(&ECNT[e[k]], 1);
            g_eidx[pe] = src[k];
            int pn = atomicAdd(&NCNT[src[k]], 1);
            g_nidx[pn] = e[k];
        }
    }
}

// ---------------- GEMM: g_xnode = x @ W^T (packed f32x2 FMA) -----------------
#define WT_STRIDE 132
#define GEMM_SMEM ((128 * WT_STRIDE + 64 * WT_STRIDE) * 4)

__device__ __forceinline__ unsigned long long fma2(unsigned long long a,
                                                   unsigned long long b,
                                                   unsigned long long c) {
    unsigned long long d;
    asm("fma.rn.f32x2 %0, %1, %2, %3;" : "=l"(d) : "l"(a), "l"(b), "l"(c));
    return d;
}

__global__ __launch_bounds__(256) void gemm_kernel(const float* __restrict__ x,
                                                   const float* __restrict__ W,
                                                   int N) {
    extern __shared__ float sm[];
    float* WT = sm;                       // [128][132], WT[k][j] = W[j][k]
    float* Xs = sm + 128 * WT_STRIDE;     // [64][132]

    int t = threadIdx.x;
    int row0 = blockIdx.x * 64;

    #pragma unroll
    for (int i = 0; i < 64; i++) {
        int idx = t + i * 256;
        int j = idx >> 7, k = idx & 127;
        WT[k * WT_STRIDE + j] = W[idx];
    }
    #pragma unroll
    for (int i = 0; i < 32; i++) {
        int idx = t + i * 256;
        int r = idx >> 7, k = idx & 127;
        int row = row0 + r;
        if (row >= N) row = N - 1;
        Xs[r * WT_STRIDE + k] = x[(size_t)row * D + k];
    }
    __syncthreads();

    int tx = t & 15, ty = t >> 4;
    int c0 = tx * 8, r0 = ty * 4;

    unsigned long long acc[4][4];
    #pragma unroll
    for (int i = 0; i < 4; i++)
        #pragma unroll
        for (int j = 0; j < 4; j++) acc[i][j] = 0ull;

    #pragma unroll 4
    for (int k = 0; k < 128; k++) {
        ulonglong2 wa = *(const ulonglong2*)(WT + k * WT_STRIDE + c0);
        ulonglong2 wb = *(const ulonglong2*)(WT + k * WT_STRIDE + c0 + 4);
        #pragma unroll
        for (int i = 0; i < 4; i++) {
            unsigned au = __float_as_uint(Xs[(r0 + i) * WT_STRIDE + k]);
            unsigned long long aa;
            asm("mov.b64 %0, {%1, %1};" : "=l"(aa) : "r"(au));
            acc[i][0] = fma2(aa, wa.x, acc[i][0]);
            acc[i][1] = fma2(aa, wa.y, acc[i][1]);
            acc[i][2] = fma2(aa, wb.x, acc[i][2]);
            acc[i][3] = fma2(aa, wb.y, acc[i][3]);
        }
    }

    #pragma unroll
    for (int i = 0; i < 4; i++) {
        int row = row0 + r0 + i;
        if (row < N) {
            ulonglong2 o0; o0.x = acc[i][0]; o0.y = acc[i][1];
            ulonglong2 o1; o1.x = acc[i][2]; o1.y = acc[i][3];
            *(ulonglong2*)(g_xnode + (size_t)row * D + c0)     = o0;
            *(ulonglong2*)(g_xnode + (size_t)row * D + c0 + 4) = o1;
            uint4 h;
            #pragma unroll
            for (int j = 0; j < 4; j++) {
                unsigned lo, hi;
                asm("mov.b64 {%0, %1}, %2;" : "=r"(lo), "=r"(hi) : "l"(acc[i][j]));
                unsigned r2;
                asm("cvt.rn.bf16x2.f32 %0, %1, %2;" : "=r"(r2)
                    : "f"(__uint_as_float(hi)), "f"(__uint_as_float(lo)));
                ((unsigned*)&h)[j] = r2;
            }
            *(uint4*)(g_xnode_h + (size_t)row * 64 + tx * 4) = h;
        }
    }
}

// ---------------- bf16x2 pair accumulate helper ------------------------------
__device__ __forceinline__ void acc_bf16x2(float4& a, uint2 u) {
    a.x += __uint_as_float(u.x << 16);
    a.y += __uint_as_float(u.x & 0xffff0000u);
    a.z += __uint_as_float(u.y << 16);
    a.w += __uint_as_float(u.y & 0xffff0000u);
}

// ---------------- phase A: warp-per-edge, shfl-distributed indices -----------
__global__ __launch_bounds__(256) void edge_agg_kernel() {
    int w = (blockIdx.x * blockDim.x + threadIdx.x) >> 5;  // edge id
    int lane = threadIdx.x & 31;
    int beg = g_eoff[w], end = g_eoff[w + 1];
    if (beg == end) return;

    float4 a0 = make_float4(0.f, 0.f, 0.f, 0.f);
    float4 a1 = make_float4(0.f, 0.f, 0.f, 0.f);

    for (int base = beg; base < end; base += 32) {
        int cnt = end - base; if (cnt > 32) cnt = 32;
        int myi = g_eidx[base + ((lane < cnt) ? lane : 0)];
        int k = 0;
        for (; k + 2 <= cnt; k += 2) {
            int n0 = __shfl_sync(0xffffffffu, myi, k);
            int n1 = __shfl_sync(0xffffffffu, myi, k + 1);
            uint2 u0 = *(const uint2*)(g_xnode_h + (size_t)n0 * 64 + lane * 2);
            uint2 u1 = *(const uint2*)(g_xnode_h + (size_t)n1 * 64 + lane * 2);
            acc_bf16x2(a0, u0);
            acc_bf16x2(a1, u1);
        }
        if (k < cnt) {
            int n0 = __shfl_sync(0xffffffffu, myi, k);
            uint2 u0 = *(const uint2*)(g_xnode_h + (size_t)n0 * 64 + lane * 2);
            acc_bf16x2(a0, u0);
        }
    }

    float inv = 1.0f / ((float)(end - beg) + EPS);
    float f0 = (a0.x + a1.x) * inv;
    float f1 = (a0.y + a1.y) * inv;
    float f2 = (a0.z + a1.z) * inv;
    float f3 = (a0.w + a1.w) * inv;
    uint2 r;
    asm("cvt.rn.bf16x2.f32 %0, %1, %2;" : "=r"(r.x) : "f"(f1), "f"(f0));
    asm("cvt.rn.bf16x2.f32 %0, %1, %2;" : "=r"(r.y) : "f"(f3), "f"(f2));
    *(uint2*)(g_heattr_h + (size_t)w * 64 + lane * 2) = r;
}

// ---------------- phase B: warp-per-node, shfl indices + fused finalize ------
__global__ __launch_bounds__(256) void node_agg_kernel(const float* __restrict__ bias,
                                                       float* __restrict__ out,
                                                       int N) {
    int w = (blockIdx.x * blockDim.x + threadIdx.x) >> 5;
    if (w >= N) return;
    int lane = threadIdx.x & 31;
    int beg = g_noff[w], end = g_noff[w + 1];

    float4 a0 = make_float4(0.f, 0.f, 0.f, 0.f);
    float4 a1 = make_float4(0.f, 0.f, 0.f, 0.f);

    for (int base = beg; base < end; base += 32) {
        int cnt = end - base; if (cnt > 32) cnt = 32;
        int myi = g_nidx[base + ((lane < cnt) ? lane : 0)];
        int k = 0;
        for (; k + 2 <= cnt; k += 2) {
            int e0 = __shfl_sync(0xffffffffu, myi, k);
            int e1 = __shfl_sync(0xffffffffu, myi, k + 1);
            uint2 u0 = *(const uint2*)(g_heattr_h + (size_t)e0 * 64 + lane * 2);
            uint2 u1 = *(const uint2*)(g_heattr_h + (size_t)e1 * 64 + lane * 2);
            acc_bf16x2(a0, u0);
            acc_bf16x2(a1, u1);
        }
        if (k < cnt) {
            int e0 = __shfl_sync(0xffffffffu, myi, k);
            uint2 u0 = *(const uint2*)(g_heattr_h + (size_t)e0 * 64 + lane * 2);
            acc_bf16x2(a0, u0);
        }
    }

    float s = 1.0f / ((float)(end - beg) + EPS);
    float4 xn = ((const float4*)g_xnode)[(size_t)w * 32 + lane];
    float4 b  = ((const float4*)bias)[lane];
    float4 o;
    o.x = (a0.x + a1.x) * s + xn.x + b.x;
    o.y = (a0.y + a1.y) * s + xn.y + b.y;
    o.z = (a0.z + a1.z) * s + xn.z + b.z;
    o.w = (a0.w + a1.w) * s + xn.w + b.w;
    ((float4*)out)[(size_t)w * 32 + lane] = o;
}

// ---------------- launch -----------------------------------------------------
extern "C" void kernel_launch(void* const* d_in, const int* in_sizes, int n_in,
                              void* d_out, int out_size) {
    const float* x    = (const float*)d_in[0];
    const void*  hidx = d_in[1];
    const float* W    = (const float*)d_in[2];
    const float* bias = (const float*)d_in[3];
    float* out = (float*)d_out;

    int N   = in_sizes[0] / D;
    int nnz = in_sizes[1] / 2;

    static cudaStream_t s2 = 0;
    static cudaEvent_t evA = 0, evB = 0;
    if (!s2) {
        cudaStreamCreateWithFlags(&s2, cudaStreamNonBlocking);
        cudaEventCreateWithFlags(&evA, cudaEventDisableTiming);
        cudaEventCreateWithFlags(&evB, cudaEventDisableTiming);
        cudaFuncSetAttribute(gemm_kernel,
                             cudaFuncAttributeMaxDynamicSharedMemorySize, GEMM_SMEM);
    }

    // fork: GEMM (+bf16 mirror) runs concurrently with CSR build
    cudaEventRecord(evA, 0);
    cudaStreamWaitEvent(s2, evA, 0);
    gemm_kernel<<<(N + 63) / 64, 256, GEMM_SMEM, s2>>>(x, W, N);

    // CSR chain on capture stream
    zero_cnts_kernel<<<(E_CAP + N_CAP) / 4 / 256, 256>>>((const int*)hidx);
    int q = (nnz + 3) / 4;
    hist_kernel<<<(q + 255) / 256, 256>>>(hidx, nnz);
    scan_local_kernel<<<NBLK_SCAN, 1024>>>();
    scan_fixup_kernel<<<NBLK_SCAN, 1024>>>();
    fill_kernel<<<(q + 255) / 256, 256>>>(hidx, nnz);

    // join
    cudaEventRecord(evB, s2);
    cudaStreamWaitEvent(0, evB, 0);

    edge_agg_kernel<<<E_CAP / 8, 256>>>();                 // warp per edge
    node_agg_kernel<<<(N + 7) / 8, 256>>>(bias, out, N);   // warp per node
}